// round 1
// baseline (speedup 1.0000x reference)
#include <cuda_runtime.h>
#include <cuda_fp16.h>
#include <cstdint>

// Problem dims
#define T_   128
#define B_   64
#define E_   300
#define H_   2048
#define G4   8192        // 4*H
#define TB   8192        // T*B
#define KP   320         // padded E per split block (mult of 64)
#define KCAT 960         // 3*KP concatenated-K for split-precision Xg GEMM

// ---------------- scratch (static __device__, allocation-free) ----------------
__device__ __align__(256) __half g_Acat[TB * KCAT];     // [x_hi | x_hi | x_lo]
__device__ __align__(256) __half g_Bcat[G4 * KCAT];     // [Wih_hi | Wih_lo | Wih_hi]
__device__ __align__(256) __half g_Whh16[G4 * H_];      // fp16 W_hh
__device__ __align__(256) float  g_Xg[TB * G4];         // 256 MB: x @ W_ih^T (no bias)
__device__ __align__(256) float  g_gates[128 * G4];     // per-step recurrent gates
__device__ __align__(256) float  g_bias[G4];            // b_ih + b_hh
__device__ __align__(256) float  g_c[128 * H_];         // cell state (fused batch 128)
__device__ __align__(256) __half g_h16[128 * H_];       // hidden state fp16 (GEMM A)

// ---------------- small helpers ----------------
__device__ __forceinline__ uint32_t smemAddr(const void* p) {
    return (uint32_t)__cvta_generic_to_shared(p);
}
__device__ __forceinline__ void ldsm4(uint32_t r[4], uint32_t addr) {
    asm volatile("ldmatrix.sync.aligned.m8n8.x4.shared.b16 {%0,%1,%2,%3}, [%4];\n"
                 : "=r"(r[0]), "=r"(r[1]), "=r"(r[2]), "=r"(r[3]) : "r"(addr));
}
__device__ __forceinline__ void mma16816(float* c, const uint32_t* a, const uint32_t* b) {
    asm volatile("mma.sync.aligned.m16n8k16.row.col.f32.f16.f16.f32 "
                 "{%0,%1,%2,%3}, {%4,%5,%6,%7}, {%8,%9}, {%0,%1,%2,%3};\n"
                 : "+f"(c[0]), "+f"(c[1]), "+f"(c[2]), "+f"(c[3])
                 : "r"(a[0]), "r"(a[1]), "r"(a[2]), "r"(a[3]), "r"(b[0]), "r"(b[1]));
}

// ---------------- prep kernels ----------------
__global__ void prep_whh(const float* __restrict__ W) {
    int i = blockIdx.x * blockDim.x + threadIdx.x;
    if (i < G4 * H_) g_Whh16[i] = __float2half(W[i]);
}

__global__ void prep_wih(const float* __restrict__ W) {
    int i = blockIdx.x * blockDim.x + threadIdx.x;
    if (i >= G4 * KP) return;
    int n = i / KP, c = i % KP;
    float w = (c < E_) ? W[n * E_ + c] : 0.f;
    __half hi = __float2half(w);
    __half lo = __float2half(w - __half2float(hi));
    g_Bcat[n * KCAT + c]          = hi;
    g_Bcat[n * KCAT + KP + c]     = lo;
    g_Bcat[n * KCAT + 2 * KP + c] = hi;
}

__global__ void prep_bias(const float* __restrict__ a, const float* __restrict__ b) {
    int i = blockIdx.x * blockDim.x + threadIdx.x;
    if (i < G4) g_bias[i] = a[i] + b[i];
}

__global__ void prep_x(const int* __restrict__ tokens, const float* __restrict__ embed) {
    int i = blockIdx.x * blockDim.x + threadIdx.x;
    if (i >= TB * KP) return;
    int row = i / KP, c = i % KP;          // row = t*64 + b (tokens is [T,B] row-major)
    int tok = tokens[row];
    float v = (c < E_) ? embed[(size_t)tok * E_ + c] : 0.f;
    __half hi = __float2half(v);
    __half lo = __float2half(v - __half2float(hi));
    g_Acat[row * KCAT + c]          = hi;
    g_Acat[row * KCAT + KP + c]     = hi;
    g_Acat[row * KCAT + 2 * KP + c] = lo;
}

__global__ void init_state() {
    int i = blockIdx.x * blockDim.x + threadIdx.x;
    if (i < 128 * H_) { g_c[i] = 0.f; g_h16[i] = __float2half(0.f); }
}

// ---------------- generic fp16 GEMM: C[M,N] = A[M,K] @ B[N,K]^T ----------------
// CTA tile 128x64, K-chunk 64, 8 warps (4 along M x 2 along N), warp tile 32x32.
__global__ __launch_bounds__(256) void gemm_kernel(
    const __half* __restrict__ A, const __half* __restrict__ B, float* __restrict__ C,
    int lda, int ldb, int ldc, int K)
{
    __shared__ __half As[128][72];   // +8 halves pad: 144B row stride, LDSM conflict-free
    __shared__ __half Bs[64][72];

    int tid  = threadIdx.x;
    int lane = tid & 31, warp = tid >> 5;
    int wm = warp & 3, wn = warp >> 2;
    int m0 = blockIdx.y * 128, n0 = blockIdx.x * 64;

    float acc[2][4][4];
#pragma unroll
    for (int mi = 0; mi < 2; mi++)
#pragma unroll
        for (int ni = 0; ni < 4; ni++)
#pragma unroll
            for (int q = 0; q < 4; q++) acc[mi][ni][q] = 0.f;

    uint32_t asB = smemAddr(As), bsB = smemAddr(Bs);
    // A ldmatrix.x4 (m16 x k16): row = wr0 + (lane&15), col = +8 halves for lanes>=16
    uint32_t aRowByte = (uint32_t)(wm * 32 + (lane & 15)) * 144;
    uint32_t aColByte = (uint32_t)((lane >> 4) << 3) * 2;
    // B ldmatrix.x4 (two k16 x n8 frags): n = wc0 + ((lane>>4)&1)*8 + (lane&7), k halves +8 for lanes 8-15/24-31
    uint32_t bRowByte = (uint32_t)(wn * 32 + ((lane >> 4) & 1) * 8 + (lane & 7)) * 144;
    uint32_t bColByte = (uint32_t)(((lane >> 3) & 1) << 3) * 2;

    for (int k0 = 0; k0 < K; k0 += 64) {
#pragma unroll
        for (int i = 0; i < 4; i++) {           // A: 128x64 halves
            int v = tid + i * 256; int r = v >> 3, cc = (v & 7) << 3;
            *(uint4*)&As[r][cc] = *(const uint4*)&A[(size_t)(m0 + r) * lda + k0 + cc];
        }
#pragma unroll
        for (int i = 0; i < 2; i++) {           // B: 64x64 halves
            int v = tid + i * 256; int r = v >> 3, cc = (v & 7) << 3;
            *(uint4*)&Bs[r][cc] = *(const uint4*)&B[(size_t)(n0 + r) * ldb + k0 + cc];
        }
        __syncthreads();
#pragma unroll
        for (int ks = 0; ks < 4; ks++) {
            uint32_t a[2][4], b[2][4];
            uint32_t ka = (uint32_t)ks * 32;    // 16 halves = 32 bytes
            ldsm4(a[0], asB + aRowByte + ka + aColByte);
            ldsm4(a[1], asB + aRowByte + 16u * 144 + ka + aColByte);
            ldsm4(b[0], bsB + bRowByte + ka + bColByte);           // n-subtiles 0,1
            ldsm4(b[1], bsB + bRowByte + 16u * 144 + ka + bColByte); // n-subtiles 2,3
#pragma unroll
            for (int mi = 0; mi < 2; mi++)
#pragma unroll
                for (int ni = 0; ni < 4; ni++)
                    mma16816(acc[mi][ni], a[mi], &b[ni >> 1][(ni & 1) * 2]);
        }
        __syncthreads();
    }

#pragma unroll
    for (int mi = 0; mi < 2; mi++) {
        int row = m0 + wm * 32 + mi * 16 + (lane >> 2);
#pragma unroll
        for (int ni = 0; ni < 4; ni++) {
            int col = n0 + wn * 32 + ni * 8 + ((lane & 3) << 1);
            float* cp = C + (size_t)row * ldc + col;
            cp[0] = acc[mi][ni][0]; cp[1] = acc[mi][ni][1];
            cp += (size_t)ldc * 8;
            cp[0] = acc[mi][ni][2]; cp[1] = acc[mi][ni][3];
        }
    }
}

// ---------------- per-step pointwise LSTM update ----------------
// Fused batch: rows 0..63 = forward samples at time s; rows 64..127 = backward
// samples at time T-1-s. Shared cell weights per reference.
__global__ __launch_bounds__(256) void pointwise(int s, const int* __restrict__ lens,
                                                 float* __restrict__ out)
{
    int idx = blockIdx.x * blockDim.x + threadIdx.x;   // 128*2048
    int m = idx >> 11, j = idx & (H_ - 1);
    int b = m & 63;
    int t = (m < 64) ? s : (T_ - 1 - s);
    const float* xg = g_Xg    + (size_t)(t * B_ + b) * G4;
    const float* gr = g_gates + (size_t)m * G4;

    float zi = gr[j]          + xg[j]          + g_bias[j];
    float zf = gr[H_ + j]     + xg[H_ + j]     + g_bias[H_ + j];
    float zg = gr[2 * H_ + j] + xg[2 * H_ + j] + g_bias[2 * H_ + j];
    float zo = gr[3 * H_ + j] + xg[3 * H_ + j] + g_bias[3 * H_ + j];

    float ig = 1.f / (1.f + expf(-zi));
    float fg = 1.f / (1.f + expf(-zf));
    float gg = tanhf(zg);
    float og = 1.f / (1.f + expf(-zo));

    float c = fg * g_c[idx] + ig * gg;
    float h = og * tanhf(c);
    g_c[idx] = c;
    g_h16[idx] = __float2half(h);

    if (m < 64) {
        if (lens[b] == s + 1) out[(size_t)b * 2 * H_ + j] = h;       // last_fwd
    } else if (s == T_ - 1) {
        out[(size_t)b * 2 * H_ + H_ + j] = h;                        // h_bwd final
    }
}

// ---------------- launch ----------------
extern "C" void kernel_launch(void* const* d_in, const int* in_sizes, int n_in,
                              void* d_out, int out_size)
{
    (void)in_sizes; (void)n_in; (void)out_size;
    const int*   tokens = (const int*)  d_in[0];
    const int*   lens   = (const int*)  d_in[1];
    const float* embed  = (const float*)d_in[2];
    const float* W_ih   = (const float*)d_in[3];
    const float* W_hh   = (const float*)d_in[4];
    const float* b_ih   = (const float*)d_in[5];
    const float* b_hh   = (const float*)d_in[6];
    float* out = (float*)d_out;

    void *pA, *pB, *pWhh, *pXg, *pG, *pH16;
    cudaGetSymbolAddress(&pA,   g_Acat);
    cudaGetSymbolAddress(&pB,   g_Bcat);
    cudaGetSymbolAddress(&pWhh, g_Whh16);
    cudaGetSymbolAddress(&pXg,  g_Xg);
    cudaGetSymbolAddress(&pG,   g_gates);
    cudaGetSymbolAddress(&pH16, g_h16);

    prep_whh <<<(G4 * H_ + 255) / 256, 256>>>(W_hh);
    prep_wih <<<(G4 * KP + 255) / 256, 256>>>(W_ih);
    prep_bias<<<(G4 + 255) / 256, 256>>>(b_ih, b_hh);
    prep_x   <<<(TB * KP + 255) / 256, 256>>>(tokens, embed);
    init_state<<<(128 * H_ + 255) / 256, 256>>>();

    // Xg = x @ W_ih^T with 3-term fp16 hi/lo split (K=960), M=8192, N=8192
    gemm_kernel<<<dim3(G4 / 64, TB / 128), 256>>>(
        (const __half*)pA, (const __half*)pB, (float*)pXg, KCAT, KCAT, G4, KCAT);

    // 128 sequential steps: gates = h16 @ W_hh16^T  (M=128, N=8192, K=2048)
    for (int s = 0; s < T_; s++) {
        gemm_kernel<<<dim3(G4 / 64, 1), 256>>>(
            (const __half*)pH16, (const __half*)pWhh, (float*)pG, H_, H_, G4, H_);
        pointwise<<<(128 * H_) / 256, 256>>>(s, lens, out);
    }
}

// round 2
// speedup vs baseline: 1.0017x; 1.0017x over previous
#include <cuda_runtime.h>
#include <cuda_fp16.h>
#include <cstdint>

// Problem dims
#define T_   128
#define B_   64
#define E_   300
#define H_   2048
#define G4   8192        // 4*H
#define TB   8192        // T*B
#define KP   320         // padded E per split block (mult of 64)
#define KCAT 960         // 3*KP concatenated-K for split-precision Xg GEMM

// ---------------- scratch (static __device__, allocation-free) ----------------
__device__ __align__(256) __half g_Acat[TB * KCAT];     // [x_hi | x_hi | x_lo]
__device__ __align__(256) __half g_Bcat[G4 * KCAT];     // [Wih_hi | Wih_lo | Wih_hi]
__device__ __align__(256) __half g_Whh16[G4 * H_];      // fp16 W_hh
__device__ __align__(256) float  g_Xg[TB * G4];         // 256 MB: x @ W_ih^T (no bias)
__device__ __align__(256) float  g_gates[128 * G4];     // per-step recurrent gates
__device__ __align__(256) float  g_bias[G4];            // b_ih + b_hh
__device__ __align__(256) float  g_c[128 * H_];         // cell state (fused batch 128)
__device__ __align__(256) __half g_h16[128 * H_];       // hidden state fp16 (GEMM A)

// ---------------- small helpers ----------------
__device__ __forceinline__ uint32_t smemAddr(const void* p) {
    return (uint32_t)__cvta_generic_to_shared(p);
}
__device__ __forceinline__ void ldsm4(uint32_t r[4], uint32_t addr) {
    asm volatile("ldmatrix.sync.aligned.m8n8.x4.shared.b16 {%0,%1,%2,%3}, [%4];\n"
                 : "=r"(r[0]), "=r"(r[1]), "=r"(r[2]), "=r"(r[3]) : "r"(addr));
}
__device__ __forceinline__ void mma16816(float* c, const uint32_t* a, const uint32_t* b) {
    asm volatile("mma.sync.aligned.m16n8k16.row.col.f32.f16.f16.f32 "
                 "{%0,%1,%2,%3}, {%4,%5,%6,%7}, {%8,%9}, {%0,%1,%2,%3};\n"
                 : "+f"(c[0]), "+f"(c[1]), "+f"(c[2]), "+f"(c[3])
                 : "r"(a[0]), "r"(a[1]), "r"(a[2]), "r"(a[3]), "r"(b[0]), "r"(b[1]));
}

// ---------------- prep kernels ----------------
__global__ void prep_whh(const float* __restrict__ W) {
    int i = blockIdx.x * blockDim.x + threadIdx.x;
    if (i < G4 * H_) g_Whh16[i] = __float2half(W[i]);
}

__global__ void prep_wih(const float* __restrict__ W) {
    int i = blockIdx.x * blockDim.x + threadIdx.x;
    if (i >= G4 * KP) return;
    int n = i / KP, c = i % KP;
    float w = (c < E_) ? W[n * E_ + c] : 0.f;
    __half hi = __float2half(w);
    __half lo = __float2half(w - __half2float(hi));
    g_Bcat[n * KCAT + c]          = hi;
    g_Bcat[n * KCAT + KP + c]     = lo;
    g_Bcat[n * KCAT + 2 * KP + c] = hi;
}

__global__ void prep_bias(const float* __restrict__ a, const float* __restrict__ b) {
    int i = blockIdx.x * blockDim.x + threadIdx.x;
    if (i < G4) g_bias[i] = a[i] + b[i];
}

__global__ void prep_x(const int* __restrict__ tokens, const float* __restrict__ embed) {
    int i = blockIdx.x * blockDim.x + threadIdx.x;
    if (i >= TB * KP) return;
    int row = i / KP, c = i % KP;          // row = t*64 + b (tokens is [T,B] row-major)
    int tok = tokens[row];
    float v = (c < E_) ? embed[(size_t)tok * E_ + c] : 0.f;
    __half hi = __float2half(v);
    __half lo = __float2half(v - __half2float(hi));
    g_Acat[row * KCAT + c]          = hi;
    g_Acat[row * KCAT + KP + c]     = hi;
    g_Acat[row * KCAT + 2 * KP + c] = lo;
}

__global__ void init_state() {
    int i = blockIdx.x * blockDim.x + threadIdx.x;
    if (i < 128 * H_) { g_c[i] = 0.f; g_h16[i] = __float2half(0.f); }
}

// ---------------- generic fp16 GEMM: C[M,N] = A[M,K] @ B[N,K]^T ----------------
// CTA tile 128x64, K-chunk 64, 8 warps (4 along M x 2 along N), warp tile 32x32.
__global__ __launch_bounds__(256) void gemm_kernel(
    const __half* __restrict__ A, const __half* __restrict__ B, float* __restrict__ C,
    int lda, int ldb, int ldc, int K)
{
    __shared__ __half As[128][72];   // +8 halves pad: 144B row stride, LDSM conflict-free
    __shared__ __half Bs[64][72];

    int tid  = threadIdx.x;
    int lane = tid & 31, warp = tid >> 5;
    int wm = warp & 3, wn = warp >> 2;
    int m0 = blockIdx.y * 128, n0 = blockIdx.x * 64;

    float acc[2][4][4];
#pragma unroll
    for (int mi = 0; mi < 2; mi++)
#pragma unroll
        for (int ni = 0; ni < 4; ni++)
#pragma unroll
            for (int q = 0; q < 4; q++) acc[mi][ni][q] = 0.f;

    uint32_t asB = smemAddr(As), bsB = smemAddr(Bs);
    // A ldmatrix.x4 (m16 x k16): row = wr0 + (lane&15), col = +8 halves for lanes>=16
    uint32_t aRowByte = (uint32_t)(wm * 32 + (lane & 15)) * 144;
    uint32_t aColByte = (uint32_t)((lane >> 4) << 3) * 2;
    // B ldmatrix.x4 (two k16 x n8 frags): n = wc0 + ((lane>>4)&1)*8 + (lane&7), k halves +8 for lanes 8-15/24-31
    uint32_t bRowByte = (uint32_t)(wn * 32 + ((lane >> 4) & 1) * 8 + (lane & 7)) * 144;
    uint32_t bColByte = (uint32_t)(((lane >> 3) & 1) << 3) * 2;

    for (int k0 = 0; k0 < K; k0 += 64) {
#pragma unroll
        for (int i = 0; i < 4; i++) {           // A: 128x64 halves
            int v = tid + i * 256; int r = v >> 3, cc = (v & 7) << 3;
            *(uint4*)&As[r][cc] = *(const uint4*)&A[(size_t)(m0 + r) * lda + k0 + cc];
        }
#pragma unroll
        for (int i = 0; i < 2; i++) {           // B: 64x64 halves
            int v = tid + i * 256; int r = v >> 3, cc = (v & 7) << 3;
            *(uint4*)&Bs[r][cc] = *(const uint4*)&B[(size_t)(n0 + r) * ldb + k0 + cc];
        }
        __syncthreads();
#pragma unroll
        for (int ks = 0; ks < 4; ks++) {
            uint32_t a[2][4], b[2][4];
            uint32_t ka = (uint32_t)ks * 32;    // 16 halves = 32 bytes
            ldsm4(a[0], asB + aRowByte + ka + aColByte);
            ldsm4(a[1], asB + aRowByte + 16u * 144 + ka + aColByte);
            ldsm4(b[0], bsB + bRowByte + ka + bColByte);           // n-subtiles 0,1
            ldsm4(b[1], bsB + bRowByte + 16u * 144 + ka + bColByte); // n-subtiles 2,3
#pragma unroll
            for (int mi = 0; mi < 2; mi++)
#pragma unroll
                for (int ni = 0; ni < 4; ni++)
                    mma16816(acc[mi][ni], a[mi], &b[ni >> 1][(ni & 1) * 2]);
        }
        __syncthreads();
    }

#pragma unroll
    for (int mi = 0; mi < 2; mi++) {
        int row = m0 + wm * 32 + mi * 16 + (lane >> 2);
#pragma unroll
        for (int ni = 0; ni < 4; ni++) {
            int col = n0 + wn * 32 + ni * 8 + ((lane & 3) << 1);
            float* cp = C + (size_t)row * ldc + col;
            cp[0] = acc[mi][ni][0]; cp[1] = acc[mi][ni][1];
            cp += (size_t)ldc * 8;
            cp[0] = acc[mi][ni][2]; cp[1] = acc[mi][ni][3];
        }
    }
}

// ---------------- per-step pointwise LSTM update ----------------
// Fused batch: rows 0..63 = forward samples at time s; rows 64..127 = backward
// samples at time T-1-s. Shared cell weights per reference.
__global__ __launch_bounds__(256) void pointwise(int s, const int* __restrict__ lens,
                                                 float* __restrict__ out)
{
    int idx = blockIdx.x * blockDim.x + threadIdx.x;   // 128*2048
    int m = idx >> 11, j = idx & (H_ - 1);
    int b = m & 63;
    int t = (m < 64) ? s : (T_ - 1 - s);
    const float* xg = g_Xg    + (size_t)(t * B_ + b) * G4;
    const float* gr = g_gates + (size_t)m * G4;

    float zi = gr[j]          + xg[j]          + g_bias[j];
    float zf = gr[H_ + j]     + xg[H_ + j]     + g_bias[H_ + j];
    float zg = gr[2 * H_ + j] + xg[2 * H_ + j] + g_bias[2 * H_ + j];
    float zo = gr[3 * H_ + j] + xg[3 * H_ + j] + g_bias[3 * H_ + j];

    float ig = 1.f / (1.f + expf(-zi));
    float fg = 1.f / (1.f + expf(-zf));
    float gg = tanhf(zg);
    float og = 1.f / (1.f + expf(-zo));

    float c = fg * g_c[idx] + ig * gg;
    float h = og * tanhf(c);
    g_c[idx] = c;
    g_h16[idx] = __float2half(h);

    if (m < 64) {
        if (lens[b] == s + 1) out[(size_t)b * 2 * H_ + j] = h;       // last_fwd
    } else if (s == T_ - 1) {
        out[(size_t)b * 2 * H_ + H_ + j] = h;                        // h_bwd final
    }
}

// ---------------- launch ----------------
extern "C" void kernel_launch(void* const* d_in, const int* in_sizes, int n_in,
                              void* d_out, int out_size)
{
    (void)in_sizes; (void)n_in; (void)out_size;
    const int*   tokens = (const int*)  d_in[0];
    const int*   lens   = (const int*)  d_in[1];
    const float* embed  = (const float*)d_in[2];
    const float* W_ih   = (const float*)d_in[3];
    const float* W_hh   = (const float*)d_in[4];
    const float* b_ih   = (const float*)d_in[5];
    const float* b_hh   = (const float*)d_in[6];
    float* out = (float*)d_out;

    void *pA, *pB, *pWhh, *pXg, *pG, *pH16;
    cudaGetSymbolAddress(&pA,   g_Acat);
    cudaGetSymbolAddress(&pB,   g_Bcat);
    cudaGetSymbolAddress(&pWhh, g_Whh16);
    cudaGetSymbolAddress(&pXg,  g_Xg);
    cudaGetSymbolAddress(&pG,   g_gates);
    cudaGetSymbolAddress(&pH16, g_h16);

    prep_whh <<<(G4 * H_ + 255) / 256, 256>>>(W_hh);
    prep_wih <<<(G4 * KP + 255) / 256, 256>>>(W_ih);
    prep_bias<<<(G4 + 255) / 256, 256>>>(b_ih, b_hh);
    prep_x   <<<(TB * KP + 255) / 256, 256>>>(tokens, embed);
    init_state<<<(128 * H_ + 255) / 256, 256>>>();

    // Xg = x @ W_ih^T with 3-term fp16 hi/lo split (K=960), M=8192, N=8192
    gemm_kernel<<<dim3(G4 / 64, TB / 128), 256>>>(
        (const __half*)pA, (const __half*)pB, (float*)pXg, KCAT, KCAT, G4, KCAT);

    // 128 sequential steps: gates = h16 @ W_hh16^T  (M=128, N=8192, K=2048)
    for (int s = 0; s < T_; s++) {
        gemm_kernel<<<dim3(G4 / 64, 1), 256>>>(
            (const __half*)pH16, (const __half*)pWhh, (float*)pG, H_, H_, G4, H_);
        pointwise<<<(128 * H_) / 256, 256>>>(s, lens, out);
    }
}